// round 1
// baseline (speedup 1.0000x reference)
#include <cuda_runtime.h>

// DFT_10316511445664 — batched 100-pt real DFT, fftshift-cropped to 50 bins, + MVN logprob.
//
// Math: X_shift[j] = FFT[j+50] = sum_n x[n]*(-1)^n * e^{-2pi i j n /100}, j in [0,50)
// out layout: x_fft [B][2][50] (re then im, each /100), followed by log_pz [B].
//
// Strategy: direct DFT with 100-entry twiddle table indexed (j*n) mod 100.
// Two rows are packed per 64-bit lane and accumulated with fma.rn.f32x2 (FFMA2),
// halving FMA-pipe pressure vs scalar FFMA. log_pz fused via smem reduction.

#define NFFT   100
#define CROP   50
#define RPB    64            // rows per block
#define PAIRS  (RPB/2)       // 32 row-pairs in smem
#define BT     400           // block threads: 8 row-groups x 50 bins

__device__ __forceinline__ unsigned long long pack2(float a, float b) {
    unsigned long long r;
    asm("mov.b64 %0, {%1, %2};" : "=l"(r) : "f"(a), "f"(b));
    return r;
}

__device__ __forceinline__ void unpack2(unsigned long long v, float& a, float& b) {
    asm("mov.b64 {%0, %1}, %2;" : "=f"(a), "=f"(b) : "l"(v));
}

__device__ __forceinline__ unsigned long long ffma2(unsigned long long a,
                                                    unsigned long long b,
                                                    unsigned long long c) {
    unsigned long long d;
    asm("fma.rn.f32x2 %0, %1, %2, %3;" : "=l"(d) : "l"(a), "l"(b), "l"(c));
    return d;
}

__global__ __launch_bounds__(BT) void dft_kernel(const float* __restrict__ x,
                                                 float* __restrict__ xfft,
                                                 float* __restrict__ logp) {
    __shared__ unsigned long long xsp[PAIRS * NFFT];   // (rowA, rowB) pairs, sign-flipped
    __shared__ unsigned long long ctt[NFFT];           // (cos, cos)
    __shared__ unsigned long long stt[NFFT];           // (-sin, -sin)
    __shared__ float ps[8][BT];                        // per-thread |z|^2 partials

    const int tid  = threadIdx.x;
    const int row0 = blockIdx.x * RPB;

    // Twiddle tables: e^{-2pi i idx/100} = cos - i sin
    if (tid < NFFT) {
        float s, c;
        sincospif((float)(2 * tid) * 0.01f, &s, &c);
        ctt[tid] = pack2(c, c);
        stt[tid] = pack2(-s, -s);
    }

    // Stage 64 rows into smem as row-pair float2, folding the (-1)^n fftshift factor.
    for (int i = tid; i < RPB * NFFT; i += BT) {
        const int r = i / NFFT;
        const int n = i - r * NFFT;
        float v = x[(size_t)(row0 + r) * NFFT + n];
        if (n & 1) v = -v;
        float* dst = reinterpret_cast<float*>(&xsp[(r >> 1) * NFFT + n]);
        dst[r & 1] = v;
    }
    __syncthreads();

    const int rb = tid / CROP;      // row-group 0..7  (rows rb*8 .. rb*8+7)
    const int j  = tid - rb * CROP; // bin 0..49
    const int p0 = rb * 4;          // first row-pair of this thread

    unsigned long long accRe[4], accIm[4];
#pragma unroll
    for (int q = 0; q < 4; ++q) { accRe[q] = 0ull; accIm[q] = 0ull; }

    int idx = 0;                    // (j*n) mod 100, incremental
#pragma unroll 4
    for (int n = 0; n < NFFT; ++n) {
        const unsigned long long cc = ctt[idx];
        const unsigned long long ss = stt[idx];
#pragma unroll
        for (int q = 0; q < 4; ++q) {
            const unsigned long long xx = xsp[(p0 + q) * NFFT + n];
            accRe[q] = ffma2(xx, cc, accRe[q]);
            accIm[q] = ffma2(xx, ss, accIm[q]);
        }
        idx += j;
        if (idx >= NFFT) idx -= NFFT;
    }

    // Epilogue: scale by 1/100, write x_fft, stash |z|^2 partials.
#pragma unroll
    for (int q = 0; q < 4; ++q) {
        float reA, reB, imA, imB;
        unpack2(accRe[q], reA, reB);
        unpack2(accIm[q], imA, imB);
        const int rA = rb * 8 + 2 * q;
        const float sreA = reA * 0.01f, simA = imA * 0.01f;
        const float sreB = reB * 0.01f, simB = imB * 0.01f;

        const size_t baseA = (size_t)(row0 + rA) * (size_t)NFFT;
        xfft[baseA + j]        = sreA;
        xfft[baseA + CROP + j] = simA;
        xfft[baseA + NFFT + j]        = sreB;
        xfft[baseA + NFFT + CROP + j] = simB;

        ps[2 * q][tid]     = sreA * sreA + simA * simA;
        ps[2 * q + 1][tid] = sreB * sreB + simB * simB;
    }
    __syncthreads();

    // Reduce 50 bins per row -> log_pz
    if (tid < RPB) {
        const int rb2 = tid >> 3;   // which row-group
        const int rl  = tid & 7;    // which row within group
        float s = 0.0f;
#pragma unroll 10
        for (int i = 0; i < CROP; ++i) s += ps[rl][rb2 * CROP + i];
        // -0.5*sum(z^2) - 0.5*100*log(2*pi)
        logp[row0 + tid] = -0.5f * s - 91.89385332046726f;
    }
}

extern "C" void kernel_launch(void* const* d_in, const int* in_sizes, int n_in,
                              void* d_out, int out_size) {
    const float* x = (const float*)d_in[0];
    const int B = in_sizes[0] / NFFT;          // 262144
    float* xf = (float*)d_out;
    float* lp = xf + (size_t)B * NFFT;
    dft_kernel<<<B / RPB, BT>>>(x, xf, lp);
}

// round 3
// speedup vs baseline: 1.6531x; 1.6531x over previous
#include <cuda_runtime.h>
#include <cuda_bf16.h>
#include <cstdint>

// DFT_10316511445664 — batched 100-pt DFT as mma.sync bf16 split-precision GEMM.
// out[B,100] = x[B,100] @ W[100,100]; W folds fftshift sign, crop, re/im split, 1/100.
// 3 K-segments: x_hi*W_hi + x_lo*W_hi + x_hi*W_lo, fp32 accumulate.
// (tcgen05 unavailable: harness PTX targets plain sm_103; mma.sync is sm_80-baseline.)

#define NFFT  100
#define CROP  50
#define MTILE 128
#define BT    256
#define KS7   7          // k16 steps per 112-wide K segment

// Precomputed B fragments, exact mma.m16n8k16 per-lane layout.
// [term(hi/lo)][ks][wn][nt][lane] -> {b0, b1}
__device__ uint2 g_bfrag[2][KS7][2][KS7][32];

__device__ __forceinline__ double wval(int k, int n) {
    if (k >= NFFT || n >= NFFT) return 0.0;
    const int j = (n < CROP) ? n : n - CROP;
    const int m = (k * j) % 100;
    double s, c;
    sincospi((double)(2 * m) / 100.0, &s, &c);
    double t = (n < CROP) ? c : -s;     // re: cos ; im: -sin
    if (k & 1) t = -t;                  // fftshift (-1)^k
    return t * 0.01;                    // 1/N_FFT
}

__global__ void winit_kernel() {
    const int i = blockIdx.x * blockDim.x + threadIdx.x;
    if (i >= 2 * KS7 * 2 * KS7 * 32) return;
    const int lane = i & 31;
    int t1 = i >> 5;
    const int nt = t1 % 7;  t1 /= 7;
    const int wn = t1 & 1;  t1 >>= 1;
    const int ks = t1 % 7;
    const int term = t1 / 7;
    const int g = lane >> 2, tg = lane & 3;
    const int n = 56 * wn + 8 * nt + g;
    uint32_t v[2];
#pragma unroll
    for (int h = 0; h < 2; ++h) {                 // b0: k rows 2tg..; b1: +8
        uint32_t p = 0;
#pragma unroll
        for (int e = 0; e < 2; ++e) {             // lo bits = even k
            const int k = ks * 16 + 2 * tg + 8 * h + e;
            const double w = wval(k, n);
            const __nv_bfloat16 bh = __float2bfloat16((float)w);
            const float fh = __bfloat162float(bh);
            const __nv_bfloat16 bl = __float2bfloat16((float)(w - (double)fh));
            const unsigned short u = (term == 0) ? __bfloat16_as_ushort(bh)
                                                 : __bfloat16_as_ushort(bl);
            p |= (uint32_t)u << (16 * e);
        }
        v[h] = p;
    }
    g_bfrag[term][ks][wn][nt][lane] = make_uint2(v[0], v[1]);
}

__device__ __forceinline__ void mma16816(uint32_t* d, const uint4& a, const uint2& b) {
    asm volatile(
        "mma.sync.aligned.m16n8k16.row.col.f32.bf16.bf16.f32 "
        "{%0,%1,%2,%3}, {%4,%5,%6,%7}, {%8,%9}, {%0,%1,%2,%3};"
        : "+r"(d[0]), "+r"(d[1]), "+r"(d[2]), "+r"(d[3])
        : "r"(a.x), "r"(a.y), "r"(a.z), "r"(a.w), "r"(b.x), "r"(b.y));
}

// A-frag smem slot: [term(2)][wm(4)][ks(7)][mt(2)][lane(32)] of uint4 -> 57344 B
#define AF_SLOT(term, wm, ks, mt, ln) (((((term)*4 + (wm))*KS7 + (ks))*2 + (mt))*32 + (ln))
#define SMEM_PS 57344

__global__ __launch_bounds__(BT, 2) void dft_mma(const float* __restrict__ x,
                                                 float* __restrict__ xfft,
                                                 float* __restrict__ logp) {
    extern __shared__ char smem[];
    uint4* const af = reinterpret_cast<uint4*>(smem);
    float* const ps = reinterpret_cast<float*>(smem + SMEM_PS);   // [128][2]

    const int tid  = threadIdx.x;
    const int wid  = tid >> 5;
    const int lane = tid & 31;
    const int row0 = blockIdx.x * MTILE;

    // Zero A-frag region (covers K padding 100..111)
    for (int i = tid; i < 3584; i += BT) af[i] = make_uint4(0, 0, 0, 0);
    __syncthreads();

    // Load x, split fp32 -> bf16 hi/lo, scatter into fragment-linear smem.
    const float2* const xg = reinterpret_cast<const float2*>(x + (size_t)row0 * NFFT);
    for (int i = tid; i < MTILE * 50; i += BT) {
        const int r = i / 50, c = i - (i / 50) * 50;
        const float2 v = xg[i];
        uint32_t hi;
        asm("cvt.rn.bf16x2.f32 %0, %1, %2;" : "=r"(hi) : "f"(v.y), "f"(v.x));
        const float h0 = __uint_as_float(hi << 16);
        const float h1 = __uint_as_float(hi & 0xffff0000u);
        uint32_t lo;
        asm("cvt.rn.bf16x2.f32 %0, %1, %2;" : "=r"(lo) : "f"(v.y - h1), "f"(v.x - h0));

        const int wm = r >> 5, mt = (r >> 4) & 1, row16 = r & 15;
        const int ks = c >> 3, cc = c & 7;
        const int reg = (row16 >> 3) | ((cc >> 2) << 1);     // a0..a3 position
        const int ln  = (row16 & 7) * 4 + (cc & 3);          // lane owning this element
        reinterpret_cast<uint32_t*>(&af[AF_SLOT(0, wm, ks, mt, ln)])[reg] = hi;
        reinterpret_cast<uint32_t*>(&af[AF_SLOT(1, wm, ks, mt, ln)])[reg] = lo;
    }
    __syncthreads();

    const int wm = wid >> 1, wn = wid & 1;

    uint32_t acc[2][7][4];
#pragma unroll
    for (int mt = 0; mt < 2; ++mt)
#pragma unroll
        for (int nt = 0; nt < 7; ++nt)
#pragma unroll
            for (int q = 0; q < 4; ++q) acc[mt][nt][q] = 0u;

    // Mainloop: 3 segments x 7 k-steps; A from smem (LDS.128), B from gmem (L1-hot).
#pragma unroll
    for (int seg = 0; seg < 3; ++seg) {
        const int at = (seg == 1) ? 1 : 0;      // A term: hi, lo, hi
        const int bt = (seg == 2) ? 1 : 0;      // B term: hi, hi, lo
#pragma unroll
        for (int ks = 0; ks < KS7; ++ks) {
            const uint4 a0 = af[AF_SLOT(at, wm, ks, 0, lane)];
            const uint4 a1 = af[AF_SLOT(at, wm, ks, 1, lane)];
            uint2 b[7];
            const uint2* const bp = &g_bfrag[bt][ks][wn][0][lane];
#pragma unroll
            for (int nt = 0; nt < 7; ++nt) b[nt] = bp[nt * 32];
#pragma unroll
            for (int nt = 0; nt < 7; ++nt) {
                mma16816(acc[0][nt], a0, b[nt]);
                mma16816(acc[1][nt], a1, b[nt]);
            }
        }
    }

    // Epilogue: direct float2 stores + fused |z|^2 partials.
    const int g = lane >> 2, tg = lane & 3;
    float s[2][2] = {{0.f, 0.f}, {0.f, 0.f}};   // [mt][row-half]
    float* const outb = xfft + (size_t)row0 * NFFT;
#pragma unroll
    for (int mt = 0; mt < 2; ++mt) {
        const int r0 = 32 * wm + 16 * mt + g;
#pragma unroll
        for (int nt = 0; nt < 7; ++nt) {
            const int c0 = 56 * wn + 8 * nt + 2 * tg;
            const float f0 = __uint_as_float(acc[mt][nt][0]);
            const float f1 = __uint_as_float(acc[mt][nt][1]);
            const float f2 = __uint_as_float(acc[mt][nt][2]);
            const float f3 = __uint_as_float(acc[mt][nt][3]);
            // Padded W cols (>=100) are exactly zero -> safe to always accumulate.
            s[mt][0] += f0 * f0 + f1 * f1;
            s[mt][1] += f2 * f2 + f3 * f3;
            if (c0 < NFFT) {
                *reinterpret_cast<float2*>(outb + (size_t)r0 * NFFT + c0)       = make_float2(f0, f1);
                *reinterpret_cast<float2*>(outb + (size_t)(r0 + 8) * NFFT + c0) = make_float2(f2, f3);
            }
        }
    }
#pragma unroll
    for (int off = 1; off <= 2; off <<= 1) {
#pragma unroll
        for (int mt = 0; mt < 2; ++mt) {
            s[mt][0] += __shfl_xor_sync(0xffffffffu, s[mt][0], off);
            s[mt][1] += __shfl_xor_sync(0xffffffffu, s[mt][1], off);
        }
    }
    if (tg == 0) {
        ps[(32 * wm + g) * 2 + wn]      = s[0][0];
        ps[(32 * wm + g + 8) * 2 + wn]  = s[0][1];
        ps[(32 * wm + 16 + g) * 2 + wn] = s[1][0];
        ps[(32 * wm + 24 + g) * 2 + wn] = s[1][1];
    }
    __syncthreads();
    if (tid < MTILE)
        logp[row0 + tid] = -0.5f * (ps[2 * tid] + ps[2 * tid + 1]) - 91.893853320467274f;
}

extern "C" void kernel_launch(void* const* d_in, const int* in_sizes, int n_in,
                              void* d_out, int out_size) {
    const float* x = (const float*)d_in[0];
    const int B = in_sizes[0] / NFFT;             // 262144
    float* xf = (float*)d_out;
    float* lp = xf + (size_t)B * NFFT;
    static bool attr_set = false;
    if (!attr_set) {
        cudaFuncSetAttribute(dft_mma, cudaFuncAttributeMaxDynamicSharedMemorySize,
                             SMEM_PS + 1024);
        attr_set = true;
    }
    winit_kernel<<<(2 * KS7 * 2 * KS7 * 32 + 255) / 256, 256>>>();
    dft_mma<<<B / MTILE, BT, SMEM_PS + 1024>>>(x, xf, lp);
}